// round 15
// baseline (speedup 1.0000x reference)
#include <cuda_runtime.h>
#include <cuda_bf16.h>
#include <cstdint>

constexpr int C_   = 192;
constexpr int H_   = 192;
constexpr int W_   = 192;
constexpr int SS_  = 4;
constexpr int NWIN = 8 * 24 * 24;   // 4608
constexpr int HW_  = H_ * W_;

__device__ float g_qkv[(size_t)NWIN * 3 * 6 * 64 * 32];  // [b_][s][h][n][d]
// pre-split weights / activations: [row][24] uint4 (8 bf16 each)
__device__ uint4 g_wqh[576 * 24], g_wql[576 * 24];
__device__ uint4 g_wph[192 * 24], g_wpl[192 * 24];
__device__ uint4 g_xhi[(size_t)NWIN * 1536], g_xlo[(size_t)NWIN * 1536];
__device__ uint4 g_ahi[(size_t)NWIN * 1536], g_alo[(size_t)NWIN * 1536];

typedef unsigned long long ull;

__device__ __forceinline__ ull dup2(float x) {
    ull r; asm("mov.b64 %0,{%1,%1};" : "=l"(r) : "f"(x)); return r;
}
__device__ __forceinline__ void upk2(ull v, float& x, float& y) {
    asm("mov.b64 {%0,%1},%2;" : "=f"(x), "=f"(y) : "l"(v));
}
__device__ __forceinline__ ull ffma2(ull a, ull b, ull c) {
    ull d; asm("fma.rn.f32x2 %0,%1,%2,%3;" : "=l"(d) : "l"(a), "l"(b), "l"(c));
    return d;
}
__device__ __forceinline__ uint32_t smem_u32(const void* p) {
    uint32_t a;
    asm("{ .reg .u64 t; cvta.to.shared.u64 t, %1; cvt.u32.u64 %0, t; }"
        : "=r"(a) : "l"(p));
    return a;
}
__device__ __forceinline__ void ldsm4(uint32_t* r, uint32_t addr) {
    asm volatile("ldmatrix.sync.aligned.m8n8.x4.shared.b16 {%0,%1,%2,%3}, [%4];"
                 : "=r"(r[0]), "=r"(r[1]), "=r"(r[2]), "=r"(r[3]) : "r"(addr));
}
__device__ __forceinline__ void mma16816(float* d, const uint32_t* a,
                                         uint32_t b0, uint32_t b1) {
    asm volatile(
        "mma.sync.aligned.m16n8k16.row.col.f32.bf16.bf16.f32 "
        "{%0,%1,%2,%3}, {%4,%5,%6,%7}, {%8,%9}, {%0,%1,%2,%3};"
        : "+f"(d[0]), "+f"(d[1]), "+f"(d[2]), "+f"(d[3])
        : "r"(a[0]), "r"(a[1]), "r"(a[2]), "r"(a[3]), "r"(b0), "r"(b1));
}
__device__ __forceinline__ void split2(float a, float b, uint32_t& hi, uint32_t& lo) {
    __nv_bfloat16 ah = __float2bfloat16(a);
    __nv_bfloat16 bh = __float2bfloat16(b);
    __nv_bfloat16 al = __float2bfloat16(a - __bfloat162float(ah));
    __nv_bfloat16 bl = __float2bfloat16(b - __bfloat162float(bh));
    hi = (uint32_t)__bfloat16_as_ushort(ah) | ((uint32_t)__bfloat16_as_ushort(bh) << 16);
    lo = (uint32_t)__bfloat16_as_ushort(al) | ((uint32_t)__bfloat16_as_ushort(bl) << 16);
}

#define CP_ASYNC16(dst, src) \
    asm volatile("cp.async.cg.shared.global [%0], [%1], 16;" :: "r"(dst), "l"(src))
#define CP_COMMIT() asm volatile("cp.async.commit_group;" ::: "memory")
#define CP_WAIT0()  asm volatile("cp.async.wait_group 0;"  ::: "memory")

// =====================================================================
// Setup A: split weights into bf16 hi/lo
// =====================================================================
__global__ void k_split_w(const float* __restrict__ qw, const float* __restrict__ pw) {
    int i = blockIdx.x * 256 + threadIdx.x;      // 0 .. 18431
    const float* src;
    uint4 *dh, *dl;
    int base;
    if (i < 13824) { src = qw; dh = g_wqh; dl = g_wql; base = i; }
    else           { src = pw; dh = g_wph; dl = g_wpl; base = i - 13824; }
    int row = base / 24, c = base % 24;
    const float* p = src + row * 192 + c * 8;
    float4 v0 = *(const float4*)p;
    float4 v1 = *(const float4*)(p + 4);
    uint32_t hi[4], lo[4];
    split2(v0.x, v0.y, hi[0], lo[0]);
    split2(v0.z, v0.w, hi[1], lo[1]);
    split2(v1.x, v1.y, hi[2], lo[2]);
    split2(v1.z, v1.w, hi[3], lo[3]);
    dh[base] = make_uint4(hi[0], hi[1], hi[2], hi[3]);
    dl[base] = make_uint4(lo[0], lo[1], lo[2], lo[3]);
}

// =====================================================================
// Setup B: gather rolled windows + split x into bf16 hi/lo panels
// =====================================================================
__global__ __launch_bounds__(256)
void k_split_x(const float* __restrict__ x) {
    __shared__ int soff[64];
    const int b_  = blockIdx.x;
    const int b   = b_ / 576;
    const int tid = threadIdx.x;
    if (tid < 64) {
        int wh = (b_ % 576) / 24, ww = b_ % 24;
        int sh = wh * 8 + (tid >> 3) + SS_; if (sh >= H_) sh -= H_;
        int sw = ww * 8 + (tid & 7)  + SS_; if (sw >= W_) sw -= W_;
        soff[tid] = sh * W_ + sw;
    }
    __syncthreads();
    const float* xb = x + (size_t)b * C_ * HW_;
    uint4* dh = g_xhi + (size_t)b_ * 1536;
    uint4* dl = g_xlo + (size_t)b_ * 1536;
    #pragma unroll
    for (int u = 0; u < 6; u++) {
        int i = tid + u * 256;
        int t = i / 24, c = i - t * 24;
        float v[8];
        #pragma unroll
        for (int j = 0; j < 8; j++) v[j] = xb[(c * 8 + j) * HW_ + soff[t]];
        uint32_t hi[4], lo[4];
        #pragma unroll
        for (int p = 0; p < 4; p++) split2(v[2 * p], v[2 * p + 1], hi[p], lo[p]);
        dh[i] = make_uint4(hi[0], hi[1], hi[2], hi[3]);
        dl[i] = make_uint4(lo[0], lo[1], lo[2], lo[3]);
    }
}

// =====================================================================
// Kernel 1: chunk-persistent QKV GEMM (unchanged from R14)
// =====================================================================
constexpr int QP_W  = 144;
constexpr int QP_NG = 32;

__global__ __launch_bounds__(256, 1)
void k_qkv_pers(const float* __restrict__ bias) {
    extern __shared__ char sm8[];
    const uint32_t sb = smem_u32(sm8);
    const int chunk = blockIdx.y;
    const int grp   = blockIdx.x;
    const int tid = threadIdx.x, warp = tid >> 5, lane = tid & 31;
    const int tt = lane & 7, sel = lane >> 3;
    const int mh = warp & 1, nq = warp >> 1;
    const int qr = lane >> 2, qc = 2 * (lane & 3);

    {
        const uint4* srch = g_wqh + (size_t)chunk * 1536;
        const uint4* srcl = g_wql + (size_t)chunk * 1536;
        #pragma unroll
        for (int u = 0; u < 6; u++) {
            int i = tid + u * 256;
            int row = i / 24, c = i - row * 24;
            *(uint4*)(sm8 + 51200 + row * 400 + c * 16)         = srch[i];
            *(uint4*)(sm8 + 51200 + 25600 + row * 400 + c * 16) = srcl[i];
        }
    }
    __syncthreads();
    uint32_t Bh[12][4], Bl[12][4];
    {
        const uint32_t bRow = (uint32_t)(nq * 16 + (sel >> 1) * 8 + tt) * 400
                              + (sel & 1) * 16;
        uint32_t bH = sb + 51200 + bRow;
        #pragma unroll
        for (int ks = 0; ks < 12; ks++) {
            ldsm4(Bh[ks], bH + ks * 32);
            ldsm4(Bl[ks], bH + 25600 + ks * 32);
        }
    }

    const int s  = chunk / 3, r3 = chunk - 3 * s;
    const int h  = 2 * r3 + (nq >> 1);
    const int dbase = (nq & 1) * 16;
    const float sc = (s == 0) ? 0.17677669529663687f : 1.0f;
    float2 bias0 = *(const float2*)&bias[chunk * 64 + nq * 16 + qc];
    float2 bias1 = *(const float2*)&bias[chunk * 64 + nq * 16 + 8 + qc];

    const int win0 = grp * QP_W;
    {
        const uint4* sh2 = g_xhi + (size_t)win0 * 1536;
        const uint4* sl2 = g_xlo + (size_t)win0 * 1536;
        #pragma unroll
        for (int u = 0; u < 6; u++) {
            int i = tid + u * 256;
            int t = i / 24, c = i - t * 24;
            CP_ASYNC16(sb + t * 400 + c * 16,         (const void*)(sh2 + i));
            CP_ASYNC16(sb + 25600 + t * 400 + c * 16, (const void*)(sl2 + i));
        }
        CP_COMMIT();
    }

    for (int i = 0; i < QP_W; i++) {
        const int win = win0 + i;
        CP_WAIT0();
        __syncthreads();
        if (i + 1 < QP_W) {
            uint32_t nb = sb + (uint32_t)((i + 1) & 1) * 51200;
            const uint4* sh2 = g_xhi + (size_t)(win + 1) * 1536;
            const uint4* sl2 = g_xlo + (size_t)(win + 1) * 1536;
            #pragma unroll
            for (int u = 0; u < 6; u++) {
                int ii = tid + u * 256;
                int t = ii / 24, c = ii - t * 24;
                CP_ASYNC16(nb + t * 400 + c * 16,         (const void*)(sh2 + ii));
                CP_ASYNC16(nb + 25600 + t * 400 + c * 16, (const void*)(sl2 + ii));
            }
        }
        CP_COMMIT();

        float acc[2][2][4];
        #pragma unroll
        for (int mt = 0; mt < 2; mt++) {
            acc[mt][0][0] = bias0.x; acc[mt][0][1] = bias0.y;
            acc[mt][0][2] = bias0.x; acc[mt][0][3] = bias0.y;
            acc[mt][1][0] = bias1.x; acc[mt][1][1] = bias1.y;
            acc[mt][1][2] = bias1.x; acc[mt][1][3] = bias1.y;
        }

        const uint32_t abase = sb + (uint32_t)(i & 1) * 51200;
        #pragma unroll
        for (int ks = 0; ks < 12; ks++) {
            #pragma unroll
            for (int mt = 0; mt < 2; mt++) {
                uint32_t ar = abase
                    + (uint32_t)(mh * 32 + mt * 16 + (sel & 1) * 8 + tt) * 400
                    + (sel >> 1) * 16 + ks * 32;
                uint32_t ah[4], al[4];
                ldsm4(ah, ar);
                ldsm4(al, ar + 25600);
                mma16816(acc[mt][0], ah, Bh[ks][0], Bh[ks][1]);
                mma16816(acc[mt][0], al, Bh[ks][0], Bh[ks][1]);
                mma16816(acc[mt][0], ah, Bl[ks][0], Bl[ks][1]);
                mma16816(acc[mt][1], ah, Bh[ks][2], Bh[ks][3]);
                mma16816(acc[mt][1], al, Bh[ks][2], Bh[ks][3]);
                mma16816(acc[mt][1], ah, Bl[ks][2], Bl[ks][3]);
            }
        }

        float* gp = g_qkv + (((size_t)win * 3 + s) * 6 + h) * 2048 + dbase;
        #pragma unroll
        for (int mt = 0; mt < 2; mt++) {
            int t0 = mh * 32 + mt * 16 + qr;
            #pragma unroll
            for (int nt = 0; nt < 2; nt++) {
                int d = nt * 8 + qc;
                *(float2*)(gp + d + t0 * 32) =
                    make_float2(acc[mt][nt][0] * sc, acc[mt][nt][1] * sc);
                *(float2*)(gp + d + (t0 + 8) * 32) =
                    make_float2(acc[mt][nt][2] * sc, acc[mt][nt][3] * sc);
            }
        }
    }
}

// =====================================================================
// Kernel 2: attention, 1 row/thread, 3 heads/CTA, 3 CTAs/SM.
// grid=(4608, 2), block=192. Warp w: local head w>>1, rows (w&1)*32+lane.
// dyn smem: ks[3*2048] + vs[3*2048] + tb[3*228] + ids = 52144 B
// =====================================================================
constexpr int AT_SMEM = (3 * 2048 * 2 + 3 * 228) * 4 + 256;

__global__ __launch_bounds__(192, 3)
void k_attn(const float* __restrict__ tbl) {
    extern __shared__ float sm[];
    float* ks = sm;                 // [3][64][32]
    float* vs = sm + 6144;          // [3][64][32]
    float* tb = sm + 12288;         // [3][228]
    int*  ids = (int*)(sm + 12288 + 684);

    const int b_  = blockIdx.x;
    const int hg  = blockIdx.y;     // head group: heads hg*3 .. hg*3+2
    const int wh  = (b_ % 576) / 24;
    const int ww  = b_ % 24;
    const int tid = threadIdx.x;
    const int warp = tid >> 5;
    const int lane = tid & 31;
    const int hl  = warp >> 1;              // local head 0..2
    const int r   = (warp & 1) * 32 + lane; // query row 0..63

    const float* base = g_qkv + (size_t)b_ * 3 * 12288;

    {   // stage K/V for 3 heads (coalesced float4 copies)
        const float4* srck = (const float4*)(base + (size_t)(6  + hg * 3) * 2048);
        const float4* srcv = (const float4*)(base + (size_t)(12 + hg * 3) * 2048);
        float4* dk = (float4*)ks;
        float4* dv = (float4*)vs;
        #pragma unroll
        for (int i = 0; i < 8; i++) {
            int idx = tid + i * 192;
            dk[idx] = srck[idx];
            dv[idx] = srcv[idx];
        }
    }
    for (int i = tid; i < 675; i += 192) {
        int h3 = i % 3, ii = i / 3;
        tb[h3 * 228 + ii] = tbl[ii * 6 + hg * 3 + h3];
    }
    if (tid < 64) {
        int ph = tid >> 3, pw = tid & 7;
        int gh = wh * 8 + ph, gw = ww * 8 + pw;
        int rh = gh < (H_ - 8) ? 0 : (gh < (H_ - 4) ? 1 : 2);
        int rw = gw < (W_ - 8) ? 0 : (gw < (W_ - 4) ? 1 : 2);
        ids[tid] = rh * 3 + rw;
    }

    // q row in registers (16 ull = 32 f)
    ull q[16];
    {
        const ull* qp = (const ull*)(base + (size_t)(hg * 3 + hl) * 2048 + (size_t)r * 32);
        #pragma unroll
        for (int i = 0; i < 16; i++) q[i] = qp[i];
    }
    __syncthreads();

    const int baseR = ((r >> 3) + 7) * 15 + ((r & 7) + 7);
    const int idn   = ids[r];
    const float* tbh = tb + hl * 228;

    float sum = 0.f;
    ull acc[16];
    #pragma unroll
    for (int i = 0; i < 16; i++) acc[i] = 0ull;

    const ulonglong2* ksr = (const ulonglong2*)(ks + hl * 2048);
    const ulonglong2* vsr = (const ulonglong2*)(vs + hl * 2048);

    #pragma unroll 4
    for (int m = 0; m < 64; m++) {
        const ulonglong2* kk = ksr + m * 8;
        ull d0 = 0, d1 = 0, d2 = 0, d3 = 0;
        #pragma unroll
        for (int i = 0; i < 4; i++) {
            ulonglong2 kv0 = kk[2 * i];
            ulonglong2 kv1 = kk[2 * i + 1];
            d0 = ffma2(q[4 * i],     kv0.x, d0);
            d1 = ffma2(q[4 * i + 1], kv0.y, d1);
            d2 = ffma2(q[4 * i + 2], kv1.x, d2);
            d3 = ffma2(q[4 * i + 3], kv1.y, d3);
        }
        float a0, a1, a2, a3, b0, b1;
        upk2(d0, a0, a1); upk2(d1, a2, a3);
        float c0, c1, c2, c3;
        upk2(d2, c0, c1); upk2(d3, c2, c3);
        int moff = (m >> 3) * 15 + (m & 7);
        float sv = ((a0 + a1) + (a2 + a3)) + ((c0 + c1) + (c2 + c3))
                   + tbh[baseR - moff]
                   - (idn != ids[m] ? 100.0f : 0.0f);
        float e = __expf(sv);
        sum += e;
        ull e2 = dup2(e);
        const ulonglong2* vv = vsr + m * 8;
        #pragma unroll
        for (int i = 0; i < 8; i++) {
            ulonglong2 vx = vv[i];
            acc[2 * i]     = ffma2(e2, vx.x, acc[2 * i]);
            acc[2 * i + 1] = ffma2(e2, vx.y, acc[2 * i + 1]);
        }
    }

    const float inv = 1.0f / sum;
    float o[32];
    #pragma unroll
    for (int i = 0; i < 16; i++) {
        upk2(acc[i], o[2 * i], o[2 * i + 1]);
        o[2 * i] *= inv; o[2 * i + 1] *= inv;
    }
    uint4* dh = g_ahi + (size_t)b_ * 1536;
    uint4* dl = g_alo + (size_t)b_ * 1536;
    const int h = hg * 3 + hl;
    #pragma unroll
    for (int j = 0; j < 4; j++) {
        uint32_t h4[4], l4[4];
        #pragma unroll
        for (int p = 0; p < 4; p++)
            split2(o[8 * j + 2 * p], o[8 * j + 2 * p + 1], h4[p], l4[p]);
        dh[r * 24 + h * 4 + j] = make_uint4(h4[0], h4[1], h4[2], h4[3]);
        dl[r * 24 + h * 4 + j] = make_uint4(l4[0], l4[1], l4[2], l4[3]);
    }
}

// =====================================================================
// Kernel 3: chunk-persistent proj GEMM + reverse-roll scatter (R14)
// =====================================================================
constexpr int PP_W  = 48;
constexpr int PP_NG = 96;

__global__ __launch_bounds__(256, 1)
void k_proj_pers(const float* __restrict__ bias, float* __restrict__ out) {
    extern __shared__ char sm8[];
    const uint32_t sb = smem_u32(sm8);
    float* res = (float*)(sm8 + 102400);   // [64 o][66 t]
    __shared__ int soff[64];
    const int chunk = blockIdx.y;
    const int grp   = blockIdx.x;
    const int tid = threadIdx.x, warp = tid >> 5, lane = tid & 31;
    const int tt = lane & 7, sel = lane >> 3;
    const int mh = warp & 1, nq = warp >> 1;
    const int qr = lane >> 2, qc = 2 * (lane & 3);

    {
        const uint4* srch = g_wph + (size_t)chunk * 1536;
        const uint4* srcl = g_wpl + (size_t)chunk * 1536;
        #pragma unroll
        for (int u = 0; u < 6; u++) {
            int i = tid + u * 256;
            int row = i / 24, c = i - row * 24;
            *(uint4*)(sm8 + 51200 + row * 400 + c * 16)         = srch[i];
            *(uint4*)(sm8 + 51200 + 25600 + row * 400 + c * 16) = srcl[i];
        }
    }
    __syncthreads();
    uint32_t Bh[12][4], Bl[12][4];
    {
        const uint32_t bRow = (uint32_t)(nq * 16 + (sel >> 1) * 8 + tt) * 400
                              + (sel & 1) * 16;
        uint32_t bH = sb + 51200 + bRow;
        #pragma unroll
        for (int ks = 0; ks < 12; ks++) {
            ldsm4(Bh[ks], bH + ks * 32);
            ldsm4(Bl[ks], bH + 25600 + ks * 32);
        }
    }

    float2 bias0 = *(const float2*)&bias[chunk * 64 + nq * 16 + qc];
    float2 bias1 = *(const float2*)&bias[chunk * 64 + nq * 16 + 8 + qc];

    const int win0 = grp * PP_W;
    {
        const uint4* sh2 = g_ahi + (size_t)win0 * 1536;
        const uint4* sl2 = g_alo + (size_t)win0 * 1536;
        #pragma unroll
        for (int u = 0; u < 6; u++) {
            int i = tid + u * 256;
            int t = i / 24, c = i - t * 24;
            CP_ASYNC16(sb + t * 400 + c * 16,         (const void*)(sh2 + i));
            CP_ASYNC16(sb + 25600 + t * 400 + c * 16, (const void*)(sl2 + i));
        }
        CP_COMMIT();
    }

    for (int i = 0; i < PP_W; i++) {
        const int win = win0 + i;
        CP_WAIT0();
        __syncthreads();
        if (tid < 64) {
            int wh = (win % 576) / 24, ww = win % 24;
            int sh = wh * 8 + (tid >> 3) + SS_; if (sh >= H_) sh -= H_;
            int sw = ww * 8 + (tid & 7)  + SS_; if (sw >= W_) sw -= W_;
            soff[tid] = sh * W_ + sw;
        }
        if (i + 1 < PP_W) {
            uint32_t nb = sb + (uint32_t)((i + 1) & 1) * 51200;
            const uint4* sh2 = g_ahi + (size_t)(win + 1) * 1536;
            const uint4* sl2 = g_alo + (size_t)(win + 1) * 1536;
            #pragma unroll
            for (int u = 0; u < 6; u++) {
                int ii = tid + u * 256;
                int t = ii / 24, c = ii - t * 24;
                CP_ASYNC16(nb + t * 400 + c * 16,         (const void*)(sh2 + ii));
                CP_ASYNC16(nb + 25600 + t * 400 + c * 16, (const void*)(sl2 + ii));
            }
        }
        CP_COMMIT();

        float acc[2][2][4];
        #pragma unroll
        for (int mt = 0; mt < 2; mt++) {
            acc[mt][0][0] = bias0.x; acc[mt][0][1] = bias0.y;
            acc[mt][0][2] = bias0.x; acc[mt][0][3] = bias0.y;
            acc[mt][1][0] = bias1.x; acc[mt][1][1] = bias1.y;
            acc[mt][1][2] = bias1.x; acc[mt][1][3] = bias1.y;
        }

        const uint32_t abase = sb + (uint32_t)(i & 1) * 51200;
        #pragma unroll
        for (int ks = 0; ks < 12; ks++) {
            #pragma unroll
            for (int mt = 0; mt < 2; mt++) {
                uint32_t ar = abase
                    + (uint32_t)(mh * 32 + mt * 16 + (sel & 1) * 8 + tt) * 400
                    + (sel >> 1) * 16 + ks * 32;
                uint32_t ah[4], al[4];
                ldsm4(ah, ar);
                ldsm4(al, ar + 25600);
                mma16816(acc[mt][0], ah, Bh[ks][0], Bh[ks][1]);
                mma16816(acc[mt][0], al, Bh[ks][0], Bh[ks][1]);
                mma16816(acc[mt][0], ah, Bl[ks][0], Bl[ks][1]);
                mma16816(acc[mt][1], ah, Bh[ks][2], Bh[ks][3]);
                mma16816(acc[mt][1], al, Bh[ks][2], Bh[ks][3]);
                mma16816(acc[mt][1], ah, Bl[ks][2], Bl[ks][3]);
            }
        }

        #pragma unroll
        for (int mt = 0; mt < 2; mt++) {
            int t0 = mh * 32 + mt * 16 + qr;
            #pragma unroll
            for (int nt = 0; nt < 2; nt++) {
                int o = nq * 16 + nt * 8 + qc;
                res[o * 66 + t0]           = acc[mt][nt][0];
                res[(o + 1) * 66 + t0]     = acc[mt][nt][1];
                res[o * 66 + t0 + 8]       = acc[mt][nt][2];
                res[(o + 1) * 66 + t0 + 8] = acc[mt][nt][3];
            }
        }
        __syncthreads();

        float* outb = out + (size_t)(win / 576) * C_ * HW_;
        #pragma unroll
        for (int it = 0; it < 16; it++) {
            int idx = tid + it * 256;
            int o = idx >> 6, t = idx & 63;
            outb[(chunk * 64 + o) * HW_ + soff[t]] = res[o * 66 + t];
        }
    }
}

// =====================================================================
extern "C" void kernel_launch(void* const* d_in, const int* in_sizes, int n_in,
                              void* d_out, int out_size) {
    const float* x      = (const float*)d_in[0];
    const float* qkv_w  = (const float*)d_in[1];
    const float* qkv_b  = (const float*)d_in[2];
    const float* proj_w = (const float*)d_in[3];
    const float* proj_b = (const float*)d_in[4];
    const float* tbl    = (const float*)d_in[5];
    float* out = (float*)d_out;

    cudaFuncSetAttribute(k_qkv_pers,  cudaFuncAttributeMaxDynamicSharedMemorySize, 102400);
    cudaFuncSetAttribute(k_attn,      cudaFuncAttributeMaxDynamicSharedMemorySize, AT_SMEM);
    cudaFuncSetAttribute(k_proj_pers, cudaFuncAttributeMaxDynamicSharedMemorySize, 119296);

    k_split_w<<<72, 256>>>(qkv_w, proj_w);
    k_split_x<<<NWIN, 256>>>(x);
    k_qkv_pers<<<dim3(QP_NG, 9), 256, 102400>>>(qkv_b);
    k_attn<<<dim3(NWIN, 2), 192, AT_SMEM>>>(tbl);
    k_proj_pers<<<dim3(PP_NG, 3), 256, 119296>>>(proj_b, out);
}